// round 10
// baseline (speedup 1.0000x reference)
#include <cuda_runtime.h>
#include <cuda_bf16.h>
#include <math.h>

typedef unsigned long long ull;
typedef unsigned int u32;
#define FFMA2(d,a,b,c) asm("fma.rn.f32x2 %0, %1, %2, %3;" : "=l"(d) : "l"(a), "l"(b), "l"(c))

#define NB 128
#define NT 256

// ---------------- scratch (device globals) ----------------
__device__ float g_featW[64 * 49 * 512];
__device__ float g_gxx [64 * 32 * 1536];
__device__ float g_W2t [512 * 512];
__device__ float g_HAT [64 * 512];
__device__ float g_GH  [64 * 1536];
__device__ float g_ctx [64 * 512];
__device__ float g_hist[64 * 32 * 512];
__device__ unsigned g_flag[128 * 32];             // per-block flags, 128B apart

// bf16-split fc operands
__device__ __nv_bfloat16 g_Abig[2048 * 1536];     // [A_hi | A_lo | A_hi]
__device__ __nv_bfloat16 g_Bbig[10240 * 1536];    // [B_hi | B_hi | B_lo], N-major, zero-padded

__device__ __forceinline__ float plo(ull v) { return __uint_as_float((unsigned)v); }
__device__ __forceinline__ float phi(ull v) { return __uint_as_float((unsigned)(v >> 32)); }

__device__ __forceinline__ float fexp2a(float x){ float y; asm("ex2.approx.ftz.f32 %0,%1;" : "=f"(y):"f"(x)); return y; }
__device__ __forceinline__ float fexpa(float x){ return fexp2a(x * 1.4426950408889634f); }
__device__ __forceinline__ float frcpa(float x){ float y; asm("rcp.approx.ftz.f32 %0,%1;" : "=f"(y):"f"(x)); return y; }
__device__ __forceinline__ float fsigmoid(float x){ return frcpa(1.f + fexpa(-x)); }
__device__ __forceinline__ float ftanh(float x){ return 1.f - 2.f * frcpa(1.f + fexpa(2.f * x)); }

__global__ void k_reset()
{
    for (int i = threadIdx.x; i < 128 * 32; i += blockDim.x) g_flag[i] = 0;
}

// ====================================================================
// Transpose attn_W[512:1024, :] -> g_W2t[n][k]
// ====================================================================
__global__ void k_transpose_w2(const float* __restrict__ attn_W)
{
    __shared__ float tile[32][33];
    int bx = blockIdx.x, by = blockIdx.y;
    int tx = threadIdx.x, ty = threadIdx.y;
#pragma unroll
    for (int i = 0; i < 4; i++) {
        int k = by * 32 + ty + i * 8;
        int j = bx * 32 + tx;
        tile[ty + i * 8][tx] = attn_W[(512 + k) * 512 + j];
    }
    __syncthreads();
#pragma unroll
    for (int i = 0; i < 4; i++) {
        int j = bx * 32 + ty + i * 8;
        int k = by * 32 + tx;
        g_W2t[j * 512 + k] = tile[tx][ty + i * 8];
    }
}

// ====================================================================
// 128x128-tile FFMA2 SGEMM (featW + gxx) — unchanged
// ====================================================================
__global__ void __launch_bounds__(256)
k_gemm128(int mode, const float* __restrict__ Aext,
          const float* __restrict__ Bmat, const float* __restrict__ bias,
          float* __restrict__ Cext,
          const float* __restrict__ embed, const int* __restrict__ captions,
          int M, int N, int K, int ldb, int ldc)
{
    const float* A; float* C;
    bool bnt = (mode == 2);
    if (mode == 0)      { A = Aext;   C = g_featW; }
    else if (mode == 1) { A = g_hist; C = Cext; }
    else                { A = nullptr; C = g_gxx; }

    __shared__ __align__(16) float2 As2[8][128];
    __shared__ __align__(16) float2 Bs2[8][128];

    int tid = threadIdx.x;
    int m0 = blockIdx.x * 128;
    int n0 = blockIdx.y * 128;
    int tx = tid & 15, ty = tid >> 4;

    int ia0 = tid, ia1 = tid + 256;
    int ar0 = ia0 >> 2, ar1 = ia1 >> 2;
    int ak0 = (ia0 & 3) * 4, ak1 = (ia1 & 3) * 4;
    const float *pArow0, *pArow1;
    if (mode == 2) {
        int m = m0 + ar0;
        pArow0 = embed + (long)captions[(m >> 5) * 33 + (m & 31)] * 512;
        m = m0 + ar1;
        pArow1 = embed + (long)captions[(m >> 5) * 33 + (m & 31)] * 512;
    } else {
        int m = min(m0 + ar0, M - 1); pArow0 = A + (long)m * 512;
        m = min(m0 + ar1, M - 1);     pArow1 = A + (long)m * 512;
    }

    int br0, bk0, br1, bk1;
    const float *pB0, *pB1;
    if (bnt) {
        br0 = ia0 >> 2; bk0 = (ia0 & 3) * 4;
        br1 = ia1 >> 2; bk1 = (ia1 & 3) * 4;
        pB0 = Bmat + (long)(n0 + br0) * ldb;
        pB1 = Bmat + (long)(n0 + br1) * ldb;
    } else {
        bk0 = ia0 >> 5; br0 = (ia0 & 31) * 4;
        bk1 = ia1 >> 5; br1 = (ia1 & 31) * 4;
        pB0 = Bmat + (long)bk0 * ldb + n0 + br0;
        pB1 = Bmat + (long)bk1 * ldb + n0 + br1;
    }
    bool nfull = (n0 + 128 <= N);

    ull acc[8][8];
#pragma unroll
    for (int i = 0; i < 8; i++)
#pragma unroll
        for (int j = 0; j < 8; j++) acc[i][j] = 0ull;

    float4 pa0 = *(const float4*)(pArow0 + ak0);
    float4 pa1 = *(const float4*)(pArow1 + ak1);
    float4 pb0, pb1;
    if (bnt) {
        pb0 = *(const float4*)(pB0 + bk0);
        pb1 = *(const float4*)(pB1 + bk1);
    } else if (nfull) {
        pb0 = *(const float4*)pB0;
        pb1 = *(const float4*)pB1;
    } else {
        int c0 = n0 + br0, c1 = n0 + br1;
        pb0.x = (c0+0<N)?pB0[0]:0.f; pb0.y = (c0+1<N)?pB0[1]:0.f;
        pb0.z = (c0+2<N)?pB0[2]:0.f; pb0.w = (c0+3<N)?pB0[3]:0.f;
        pb1.x = (c1+0<N)?pB1[0]:0.f; pb1.y = (c1+1<N)?pB1[1]:0.f;
        pb1.z = (c1+2<N)?pB1[2]:0.f; pb1.w = (c1+3<N)?pB1[3]:0.f;
    }

    for (int k0 = 0; k0 < K; k0 += 16) {
        As2[(ak0 >> 1)    ][ar0] = make_float2(pa0.x, pa0.y);
        As2[(ak0 >> 1) + 1][ar0] = make_float2(pa0.z, pa0.w);
        As2[(ak1 >> 1)    ][ar1] = make_float2(pa1.x, pa1.y);
        As2[(ak1 >> 1) + 1][ar1] = make_float2(pa1.z, pa1.w);
        if (bnt) {
            Bs2[(bk0 >> 1)    ][br0] = make_float2(pb0.x, pb0.y);
            Bs2[(bk0 >> 1) + 1][br0] = make_float2(pb0.z, pb0.w);
            Bs2[(bk1 >> 1)    ][br1] = make_float2(pb1.x, pb1.y);
            Bs2[(bk1 >> 1) + 1][br1] = make_float2(pb1.z, pb1.w);
        } else {
            float* q0 = (float*)&Bs2[bk0 >> 1][br0] + (bk0 & 1);
            q0[0] = pb0.x; q0[2] = pb0.y; q0[4] = pb0.z; q0[6] = pb0.w;
            float* q1 = (float*)&Bs2[bk1 >> 1][br1] + (bk1 & 1);
            q1[0] = pb1.x; q1[2] = pb1.y; q1[4] = pb1.z; q1[6] = pb1.w;
        }
        __syncthreads();

        if (k0 + 16 < K) {
            int kn = k0 + 16;
            pa0 = *(const float4*)(pArow0 + kn + ak0);
            pa1 = *(const float4*)(pArow1 + kn + ak1);
            if (bnt) {
                pb0 = *(const float4*)(pB0 + kn + bk0);
                pb1 = *(const float4*)(pB1 + kn + bk1);
            } else if (nfull) {
                pb0 = *(const float4*)(pB0 + (long)kn * ldb);
                pb1 = *(const float4*)(pB1 + (long)kn * ldb);
            } else {
                const float* r0 = pB0 + (long)kn * ldb;
                const float* r1 = pB1 + (long)kn * ldb;
                int c0 = n0 + br0, c1 = n0 + br1;
                pb0.x = (c0+0<N)?r0[0]:0.f; pb0.y = (c0+1<N)?r0[1]:0.f;
                pb0.z = (c0+2<N)?r0[2]:0.f; pb0.w = (c0+3<N)?r0[3]:0.f;
                pb1.x = (c1+0<N)?r1[0]:0.f; pb1.y = (c1+1<N)?r1[1]:0.f;
                pb1.z = (c1+2<N)?r1[2]:0.f; pb1.w = (c1+3<N)?r1[3]:0.f;
            }
        }

#pragma unroll
        for (int kp = 0; kp < 8; kp++) {
            ull a[8], b[8];
#pragma unroll
            for (int g = 0; g < 4; g++) {
                ulonglong2 av = *(const ulonglong2*)&As2[kp][g * 32 + ty * 2];
                a[g * 2] = av.x; a[g * 2 + 1] = av.y;
                ulonglong2 bv = *(const ulonglong2*)&Bs2[kp][g * 32 + tx * 2];
                b[g * 2] = bv.x; b[g * 2 + 1] = bv.y;
            }
#pragma unroll
            for (int i = 0; i < 8; i++)
#pragma unroll
                for (int j = 0; j < 8; j++)
                    FFMA2(acc[i][j], a[i], b[j], acc[i][j]);
        }
        __syncthreads();
    }

#pragma unroll
    for (int i = 0; i < 8; i++) {
        int mi = m0 + (i >> 1) * 32 + ty * 2 + (i & 1);
        if (mi >= M) continue;
#pragma unroll
        for (int j = 0; j < 8; j += 2) {
            int nj = n0 + (j >> 1) * 32 + tx * 2;
            if (nj + 1 < N) {
                float2 v;
                v.x = plo(acc[i][j])     + phi(acc[i][j])     + bias[nj];
                v.y = plo(acc[i][j + 1]) + phi(acc[i][j + 1]) + bias[nj + 1];
                *(float2*)&C[(long)mi * ldc + nj] = v;
            } else if (nj < N) {
                C[(long)mi * ldc + nj] = plo(acc[i][j]) + phi(acc[i][j]) + bias[nj];
            }
        }
    }
}

// ====================================================================
// Flag-array grid barrier: per-block release-store to own 128B-spaced
// flag; waiters poll all flags in parallel (no atomics at all).
// Values are monotonic (3t+phase), so >= comparison is safe.
// ====================================================================
__device__ __forceinline__ void bar_arrive(int bid, unsigned val)
{
    __syncthreads();
    if (threadIdx.x == 0)
        asm volatile("st.release.gpu.global.u32 [%0], %1;"
                     :: "l"(&g_flag[bid * 32]), "r"(val) : "memory");
}

__device__ __forceinline__ void bar_wait(int nflags, unsigned val)
{
    if (threadIdx.x < nflags) {
        unsigned v;
        do {
            asm volatile("ld.acquire.gpu.global.u32 %0, [%1];"
                         : "=r"(v) : "l"(&g_flag[threadIdx.x * 32]));
        } while ((int)(v - val) < 0);
    }
    __syncthreads();
}

// ====================================================================
// Persistent fused loop — R7/R9 structure, flag barrier + fused convA.
//   blocks 0-63 : HAT (8 cols) -> b1(64) -> attention -> b2 -> P3 -> b3
//   blocks 64-127: GH (24 cols) ----------------------> b2 -> P3 -> b3
// ====================================================================
#define WST 520
#define HSS 136

__global__ void __launch_bounds__(NT)
k_loop(const float* __restrict__ features, const float* __restrict__ v_w,
       const float* __restrict__ W_hh, const float* __restrict__ W_ih,
       const float* __restrict__ b_hh)
{
    extern __shared__ float sm[];
    float* sW1 = sm;                       // up to 24 x WST (P1 weights)
    float* sW3 = sm + 24 * WST;            // 12 x WST (P3 weights)
    float* hs  = sm + 36 * WST;            // 64 x HSS stage / attn scratch

    int tid = threadIdx.x;
    int bid = blockIdx.x;
    bool light = (bid < 64);
    int j0 = bid * 4;

    if (light) {
        int cb = bid * 8;
        for (int i = tid; i < 8 * 512; i += NT) {
            int nl = i >> 9, k = i & 511;
            sW1[nl * WST + k] = g_W2t[(cb + nl) * 512 + k];
        }
    } else {
        int cb = (bid - 64) * 24;
        for (int i = tid; i < 24 * 512; i += NT) {
            int nl = i >> 9, k = i & 511;
            sW1[nl * WST + k] = W_hh[(long)(cb + nl) * 512 + k];
        }
    }
    for (int i = tid; i < 12 * 512; i += NT) {
        int rl = i >> 9, k = i & 511;
        int gate = rl >> 2, jl = rl & 3;
        sW3[rl * WST + k] = W_ih[(long)(gate * 512 + j0 + jl) * 1024 + 512 + k];
    }
    __syncthreads();

    int bq = tid >> 3;
    int nq = tid & 7;
    int b3 = tid >> 2;
    int jl3 = tid & 3;

    for (int t = 0; t < 32; t++) {
        // ================== P1 ==================
        if (light) {
            ull a0 = 0, a1 = 0;
            for (int c = 0; c < 4; c++) {
                for (int i = tid; i < 2048; i += NT) {
                    int b = i >> 5;
                    int kq4 = (i & 31) << 2;
                    float4 v;
                    if (t == 0) v = make_float4(0.f, 0.f, 0.f, 0.f);
                    else v = *(const float4*)&g_hist[(long)(b * 32 + t - 1) * 512 + c * 128 + kq4];
                    *(float4*)&hs[b * HSS + kq4] = v;
                }
                __syncthreads();
                const float* ap0 = &hs[(bq * 2) * HSS];
                const float* ap1 = ap0 + HSS;
                const float* wp  = &sW1[nq * WST + c * 128];
#pragma unroll 8
                for (int j = 0; j < 32; j++) {
                    ulonglong2 av0 = *(const ulonglong2*)(ap0 + 4 * j);
                    ulonglong2 av1 = *(const ulonglong2*)(ap1 + 4 * j);
                    ulonglong2 wv  = *(const ulonglong2*)(wp  + 4 * j);
                    FFMA2(a0, av0.x, wv.x, a0); FFMA2(a0, av0.y, wv.y, a0);
                    FFMA2(a1, av1.x, wv.x, a1); FFMA2(a1, av1.y, wv.y, a1);
                }
                __syncthreads();
            }
            int n = bid * 8 + nq;
            g_HAT[(bq * 2) * 512 + n]     = plo(a0) + phi(a0);
            g_HAT[(bq * 2 + 1) * 512 + n] = plo(a1) + phi(a1);

            bar_arrive(bid, 3 * t + 1);
            bar_wait(64, 3 * t + 1);     // b1: HAT visible (light only)

            // ============ P2: attention (b = bid) ============
            {
                int b = bid;
                float* hat = hs;
                float* vw  = hs + 512;
                float* sc  = hs + 1024;
                for (int j = tid; j < 512; j += NT) {
                    hat[j] = g_HAT[b * 512 + j];
                    vw[j]  = v_w[j];
                }
                __syncthreads();
                int warp = tid >> 5, lane = tid & 31;
                for (int r = warp; r < 49; r += 8) {
                    const float* fw = g_featW + (long)(b * 49 + r) * 512;
                    float p = 0.f;
                    for (int j = lane; j < 512; j += 32)
                        p += ftanh(fw[j] + hat[j]) * vw[j];
#pragma unroll
                    for (int o = 16; o; o >>= 1) p += __shfl_xor_sync(0xffffffffu, p, o);
                    if (lane == 0) sc[r] = p;
                }
                __syncthreads();
                if (tid < 32) {
                    float s0 = (tid < 49) ? sc[tid] : -1e30f;
                    float s1 = (tid + 32 < 49) ? sc[tid + 32] : -1e30f;
                    float mx = fmaxf(s0, s1);
#pragma unroll
                    for (int o = 16; o; o >>= 1) mx = fmaxf(mx, __shfl_xor_sync(0xffffffffu, mx, o));
                    float e0 = (tid < 49) ? fexpa(s0 - mx) : 0.f;
                    float e1 = (tid + 32 < 49) ? fexpa(s1 - mx) : 0.f;
                    float s = e0 + e1;
#pragma unroll
                    for (int o = 16; o; o >>= 1) s += __shfl_xor_sync(0xffffffffu, s, o);
                    float inv = 1.f / s;
                    if (tid < 49) sc[tid] = e0 * inv;
                    if (tid + 32 < 49) sc[tid + 32] = e1 * inv;
                }
                __syncthreads();
                for (int j = tid; j < 512; j += NT) {
                    const float* fb = features + (long)b * 49 * 512 + j;
                    float acc = 0.f;
#pragma unroll 7
                    for (int r = 0; r < 49; r++) acc = fmaf(sc[r], fb[r * 512], acc);
                    g_ctx[b * 512 + j] = acc;
                }
            }
        } else {
            // heavy: GH, 24 cols (thread: 2b x 3n)
            ull a00 = 0, a01 = 0, a02 = 0, a10 = 0, a11 = 0, a12 = 0;
            for (int c = 0; c < 4; c++) {
                for (int i = tid; i < 2048; i += NT) {
                    int b = i >> 5;
                    int kq4 = (i & 31) << 2;
                    float4 v;
                    if (t == 0) v = make_float4(0.f, 0.f, 0.f, 0.f);
                    else v = *(const float4*)&g_hist[(long)(b * 32 + t - 1) * 512 + c * 128 + kq4];
                    *(float4*)&hs[b * HSS + kq4] = v;
                }
                __syncthreads();
                const float* ap0 = &hs[(bq * 2) * HSS];
                const float* ap1 = ap0 + HSS;
                const float* wp0 = &sW1[(nq * 3 + 0) * WST + c * 128];
                const float* wp1 = wp0 + WST;
                const float* wp2 = wp1 + WST;
#pragma unroll 4
                for (int j = 0; j < 32; j++) {
                    ulonglong2 av0 = *(const ulonglong2*)(ap0 + 4 * j);
                    ulonglong2 av1 = *(const ulonglong2*)(ap1 + 4 * j);
                    ulonglong2 w0 = *(const ulonglong2*)(wp0 + 4 * j);
                    ulonglong2 w1 = *(const ulonglong2*)(wp1 + 4 * j);
                    ulonglong2 w2 = *(const ulonglong2*)(wp2 + 4 * j);
                    FFMA2(a00, av0.x, w0.x, a00); FFMA2(a00, av0.y, w0.y, a00);
                    FFMA2(a01, av0.x, w1.x, a01); FFMA2(a01, av0.y, w1.y, a01);
                    FFMA2(a02, av0.x, w2.x, a02); FFMA2(a02, av0.y, w2.y, a02);
                    FFMA2(a10, av1.x, w0.x, a10); FFMA2(a10, av1.y, w0.y, a10);
                    FFMA2(a11, av1.x, w1.x, a11); FFMA2(a11, av1.y, w1.y, a11);
                    FFMA2(a12, av1.x, w2.x, a12); FFMA2(a12, av1.y, w2.y, a12);
                }
                __syncthreads();
            }
            int col = (bid - 64) * 24 + nq * 3;
            int b0 = bq * 2, b1r = bq * 2 + 1;
            g_GH[b0 * 1536 + col]     = plo(a00) + phi(a00);
            g_GH[b0 * 1536 + col + 1] = plo(a01) + phi(a01);
            g_GH[b0 * 1536 + col + 2] = plo(a02) + phi(a02);
            g_GH[b1r * 1536 + col]     = plo(a10) + phi(a10);
            g_GH[b1r * 1536 + col + 1] = plo(a11) + phi(a11);
            g_GH[b1r * 1536 + col + 2] = plo(a12) + phi(a12);
        }

        bar_arrive(bid, 3 * t + 2);
        bar_wait(128, 3 * t + 2);        // b2: ctx + GH ready

        // ================== P3: GX + GRU combine ==================
        ull cr = 0, cz = 0, cn = 0;
        for (int c = 0; c < 4; c++) {
            for (int i = tid; i < 2048; i += NT) {
                int b = i >> 5;
                int kq4 = (i & 31) << 2;
                *(float4*)&hs[b * HSS + kq4] =
                    *(const float4*)&g_ctx[b * 512 + c * 128 + kq4];
            }
            __syncthreads();
            const float* ap = &hs[b3 * HSS];
            const float* wr = &sW3[(0 + jl3) * WST + c * 128];
            const float* wz = &sW3[(4 + jl3) * WST + c * 128];
            const float* wn = &sW3[(8 + jl3) * WST + c * 128];
#pragma unroll 8
            for (int j = 0; j < 32; j++) {
                ulonglong2 av = *(const ulonglong2*)(ap + 4 * j);
                ulonglong2 w0 = *(const ulonglong2*)(wr + 4 * j);
                ulonglong2 w1 = *(const ulonglong2*)(wz + 4 * j);
                ulonglong2 w2 = *(const ulonglong2*)(wn + 4 * j);
                FFMA2(cr, av.x, w0.x, cr); FFMA2(cr, av.y, w0.y, cr);
                FFMA2(cz, av.x, w1.x, cz); FFMA2(cz, av.y, w1.y, cz);
                FFMA2(cn, av.x, w2.x, cn); FFMA2(cn, av.y, w2.y, cn);
            }
            __syncthreads();
        }
        {
            int j = j0 + jl3;
            int b = b3;
            int m = b * 32 + t;
            float xr = plo(cr) + phi(cr);
            float xz = plo(cz) + phi(cz);
            float xn = plo(cn) + phi(cn);
            float gxr = g_gxx[(long)m * 1536 + j]        + xr;
            float gxz = g_gxx[(long)m * 1536 + 512 + j]  + xz;
            float gxn = g_gxx[(long)m * 1536 + 1024 + j] + xn;
            float ghr = g_GH[b * 1536 + j]        + b_hh[j];
            float ghz = g_GH[b * 1536 + 512 + j]  + b_hh[512 + j];
            float ghn = g_GH[b * 1536 + 1024 + j] + b_hh[1024 + j];
            float rg = fsigmoid(gxr + ghr);
            float zg = fsigmoid(gxz + ghz);
            float ng = ftanh(gxn + rg * ghn);
            float hp = (t == 0) ? 0.f : g_hist[(long)(m - 1) * 512 + j];
            float hnew = (1.f - zg) * ng + zg * hp;
            g_hist[(long)m * 512 + j] = hnew;
            // fused convA: bf16 split [A_hi | A_lo | A_hi]
            __nv_bfloat16 hi = __float2bfloat16_rn(hnew);
            __nv_bfloat16 lo = __float2bfloat16_rn(hnew - __bfloat162float(hi));
            g_Abig[(long)m * 1536 + j]        = hi;
            g_Abig[(long)m * 1536 + 512 + j]  = lo;
            g_Abig[(long)m * 1536 + 1024 + j] = hi;
        }

        bar_arrive(bid, 3 * t + 3);
        bar_wait(128, 3 * t + 3);        // b3: h_t visible
    }
}

// ====================================================================
// bf16 split conversion for B (fc weights)
// ====================================================================
__global__ void k_convB(const float* __restrict__ fc_W)
{
    __shared__ float tile[32][33];
    int n0 = blockIdx.x * 32, k0 = blockIdx.y * 32;
    int tx = threadIdx.x, ty = threadIdx.y;
#pragma unroll
    for (int i = 0; i < 4; i++) {
        int k = k0 + ty + i * 8;
        int n = n0 + tx;
        tile[ty + i * 8][tx] = (n < 10000) ? fc_W[(long)k * 10000 + n] : 0.f;
    }
    __syncthreads();
#pragma unroll
    for (int i = 0; i < 4; i++) {
        int n = n0 + ty + i * 8;
        int k = k0 + tx;
        float v = tile[tx][ty + i * 8];
        __nv_bfloat16 hi = __float2bfloat16_rn(v);
        __nv_bfloat16 lo = __float2bfloat16_rn(v - __bfloat162float(hi));
        g_Bbig[(long)n * 1536 + k]        = hi;
        g_Bbig[(long)n * 1536 + 512 + k]  = hi;
        g_Bbig[(long)n * 1536 + 1024 + k] = lo;
    }
}

// ====================================================================
// fc GEMM via mma.sync bf16 + cp.async double-buffered — unchanged (R9)
// ====================================================================
#define LDSM4(r0,r1,r2,r3,addr) \
    asm volatile("ldmatrix.sync.aligned.m8n8.x4.shared.b16 {%0,%1,%2,%3}, [%4];" \
        : "=r"(r0), "=r"(r1), "=r"(r2), "=r"(r3) : "r"(addr))

#define MMA16816(d,a0,a1,a2,a3,b0,b1) \
    asm volatile("mma.sync.aligned.m16n8k16.row.col.f32.bf16.bf16.f32 " \
        "{%0,%1,%2,%3}, {%4,%5,%6,%7}, {%8,%9}, {%0,%1,%2,%3};" \
        : "+f"((d)[0]), "+f"((d)[1]), "+f"((d)[2]), "+f"((d)[3]) \
        : "r"(a0), "r"(a1), "r"(a2), "r"(a3), "r"(b0), "r"(b1))

#define CPA16(saddr, gptr) \
    asm volatile("cp.async.cg.shared.global [%0], [%1], 16;" :: "r"(saddr), "l"(gptr))

#define FC_ABUF 18432u
#define FC_BBASE (2u * FC_ABUF)
#define FC_SMEM (4u * FC_ABUF)

#define FC_ISSUE(chv, bufv)                                                     \
    do {                                                                         \
        int _cb = (chv) * 64;                                                    \
        _Pragma("unroll")                                                        \
        for (int _p = 0; _p < 4; _p++) {                                         \
            int _i = tid + _p * 256;                                             \
            int _row = _i >> 3, _c = _i & 7;                                     \
            CPA16(sb + (bufv) * FC_ABUF + _row * 144 + _c * 16,                  \
                  gA + (long)_row * 1536 + _cb + _c * 8);                        \
            CPA16(sb + FC_BBASE + (bufv) * FC_ABUF + _row * 144 + _c * 16,       \
                  gB + (long)_row * 1536 + _cb + _c * 8);                        \
        }                                                                        \
    } while (0)

__global__ void __launch_bounds__(256)
k_fc_mma(const float* __restrict__ fc_b, float* __restrict__ out)
{
    extern __shared__ __align__(16) char smc[];
    u32 sb;
    asm("{ .reg .u64 t; cvta.to.shared.u64 t, %1; cvt.u32.u64 %0, t; }" : "=r"(sb) : "l"(smc));

    int tid = threadIdx.x;
    int wid = tid >> 5, lane = tid & 31;
    int m0 = blockIdx.x * 128;
    int n0 = blockIdx.y * 128;
    int wm = (wid >> 2) * 64;
    int wn = (wid & 3) * 32;

    const __nv_bfloat16* gA = g_Abig + (long)m0 * 1536;
    const __nv_bfloat16* gB = g_Bbig + (long)n0 * 1536;

    u32 lmoff = (lane & 15) * 144 + (lane >> 4) * 16;

    float acc[4][4][4];
#pragma unroll
    for (int i = 0; i < 4; i++)
#pragma unroll
        for (int j = 0; j < 4; j++)
#pragma unroll
            for (int c = 0; c < 4; c++) acc[i][j][c] = 0.f;

    FC_ISSUE(0, 0);
    asm volatile("cp.async.commit_group;" ::: "memory");
    FC_ISSUE(1, 1);
    asm volatile("cp.async.commit_group;" ::: "memory");

    for (int ch = 0; ch < 24; ch++) {
        u32 buf = ch & 1;
        asm volatile("cp.async.wait_group 1;" ::: "memory");
        __syncthreads();

        u32 abase = sb + buf * FC_ABUF + wm * 144 + lmoff;
        u32 bbase = sb + FC_BBASE + buf * FC_ABUF + wn * 144 + lmoff;
#pragma unroll
        for (int ks = 0; ks < 4; ks++) {
            u32 a[4][4], b[2][4];
#pragma unroll
            for (int mt = 0; mt < 4; mt++)
                LDSM4(a[mt][0], a[mt][1], a[mt][2], a[mt][3],
                      abase + mt * (16 * 144) + ks * 32);
#pragma unroll
            for (int nt2 = 0; nt2 < 2; nt2++)
                LDSM4(b[nt2][0], b[nt2][1], b[nt2][2], b[nt2][3],
                      bbase + nt2 * (16 * 144) + ks * 32);
#pragma unroll
            for (int mt = 0; mt < 4; mt++)
#pragma unroll
                for (int nt = 0; nt < 4; nt++) {
                    int n2 = nt >> 1, ns = nt & 1;
                    MMA16816(acc[mt][nt], a[mt][0], a[mt][1], a[mt][2], a[mt][3],
                             b[n2][ns], b[n2][ns + 2]);
                }
        }
        __syncthreads();

        if (ch + 2 < 24) FC_ISSUE(ch + 2, buf);
        asm volatile("cp.async.commit_group;" ::: "memory");
    }

#pragma unroll
    for (int mt = 0; mt < 4; mt++) {
        int rm = m0 + wm + mt * 16 + (lane >> 2);
#pragma unroll
        for (int nt = 0; nt < 4; nt++) {
            int cn = n0 + wn + nt * 8 + (lane & 3) * 2;
            if (cn < 10000) {
                float2 v0, v1;
                float bb0 = fc_b[cn], bb1 = fc_b[cn + 1];
                v0.x = acc[mt][nt][0] + bb0; v0.y = acc[mt][nt][1] + bb1;
                v1.x = acc[mt][nt][2] + bb0; v1.y = acc[mt][nt][3] + bb1;
                *(float2*)&out[(long)rm * 10000 + cn] = v0;
                *(float2*)&out[(long)(rm + 8) * 10000 + cn] = v1;
            }
        }
    }
}

// ====================================================================
extern "C" void kernel_launch(void* const* d_in, const int* in_sizes, int n_in,
                              void* d_out, int out_size)
{
    const float* features = (const float*)d_in[0];
    const int*   captions = (const int*)d_in[1];
    const float* embed    = (const float*)d_in[2];
    const float* attn_W   = (const float*)d_in[3];
    const float* attn_b   = (const float*)d_in[4];
    const float* v_w      = (const float*)d_in[5];
    const float* W_ih     = (const float*)d_in[6];
    const float* W_hh     = (const float*)d_in[7];
    const float* b_ih     = (const float*)d_in[8];
    const float* b_hh     = (const float*)d_in[9];
    const float* fc_W     = (const float*)d_in[10];
    const float* fc_b     = (const float*)d_in[11];
    float* out = (float*)d_out;

    const int LOOP_SMEM = (36 * WST + 64 * HSS) * 4;   // 109,696 B
    cudaFuncSetAttribute(k_loop, cudaFuncAttributeMaxDynamicSharedMemorySize, LOOP_SMEM);
    cudaFuncSetAttribute(k_fc_mma, cudaFuncAttributeMaxDynamicSharedMemorySize, FC_SMEM);

    k_reset<<<1, 256>>>();
    k_transpose_w2<<<dim3(16, 16), dim3(32, 8)>>>(attn_W);

    // featW = features @ attn_W[:512] + attn_b
    k_gemm128<<<dim3(25, 4), 256>>>(0, features, attn_W, attn_b, nullptr,
                                    nullptr, nullptr, 3136, 512, 512, 512, 512);

    // gx_x = gather(embed, captions) @ W_ih[:, :512]^T + b_ih
    k_gemm128<<<dim3(16, 12), 256>>>(2, nullptr, W_ih, b_ih, nullptr,
                                     embed, captions, 2048, 1536, 512, 1024, 1536);

    // B' split
    k_convB<<<dim3(320, 16), dim3(32, 8)>>>(fc_W);

    // persistent fused 32-step scan (flag barriers + fused convA)
    k_loop<<<NB, NT, LOOP_SMEM>>>(features, v_w, W_hh, W_ih, b_hh);

    // out = Abig @ Bbig^T + fc_b  (tensor cores, cp.async pipeline)
    k_fc_mma<<<dim3(16, 80), 256, FC_SMEM>>>(fc_b, out);
}

// round 11
// speedup vs baseline: 1.0433x; 1.0433x over previous
#include <cuda_runtime.h>
#include <cuda_bf16.h>
#include <math.h>

typedef unsigned long long ull;
typedef unsigned int u32;
#define FFMA2(d,a,b,c) asm("fma.rn.f32x2 %0, %1, %2, %3;" : "=l"(d) : "l"(a), "l"(b), "l"(c))

#define NB 128
#define NT 256

// ---------------- scratch (device globals) ----------------
__device__ float g_featW[64 * 49 * 512];
__device__ float g_gxx [64 * 32 * 1536];
__device__ float g_W2t [512 * 512];
__device__ float g_HAT [64 * 512];
__device__ float g_GH  [64 * 1536];
__device__ float g_ctx [64 * 512];
__device__ float g_hist[64 * 32 * 512];
__device__ unsigned g_arr[96];                    // arrive counters (idx*32)
__device__ unsigned g_rel[96];                    // release flags   (idx*32)

// bf16-split fc operands
__device__ __nv_bfloat16 g_Abig[2048 * 1536];     // [A_hi | A_lo | A_hi]
__device__ __nv_bfloat16 g_Bbig[10240 * 1536];    // [B_hi | B_hi | B_lo], N-major, zero-padded

__device__ __forceinline__ float plo(ull v) { return __uint_as_float((unsigned)v); }
__device__ __forceinline__ float phi(ull v) { return __uint_as_float((unsigned)(v >> 32)); }

__device__ __forceinline__ float fexp2a(float x){ float y; asm("ex2.approx.ftz.f32 %0,%1;" : "=f"(y):"f"(x)); return y; }
__device__ __forceinline__ float fexpa(float x){ return fexp2a(x * 1.4426950408889634f); }
__device__ __forceinline__ float frcpa(float x){ float y; asm("rcp.approx.ftz.f32 %0,%1;" : "=f"(y):"f"(x)); return y; }
__device__ __forceinline__ float fsigmoid(float x){ return frcpa(1.f + fexpa(-x)); }
__device__ __forceinline__ float ftanh(float x){ return 1.f - 2.f * frcpa(1.f + fexpa(2.f * x)); }

// ====================================================================
// Transpose attn_W[512:1024, :] -> g_W2t[n][k]  (also resets barriers)
// ====================================================================
__global__ void k_transpose_w2(const float* __restrict__ attn_W)
{
    __shared__ float tile[32][33];
    int bx = blockIdx.x, by = blockIdx.y;
    int tx = threadIdx.x, ty = threadIdx.y;
    if (bx == 0 && by == 0 && ty == 0) {
        for (int i = tx; i < 96; i += 32) { g_arr[i] = 0; g_rel[i] = 0; }
    }
#pragma unroll
    for (int i = 0; i < 4; i++) {
        int k = by * 32 + ty + i * 8;
        int j = bx * 32 + tx;
        tile[ty + i * 8][tx] = attn_W[(512 + k) * 512 + j];
    }
    __syncthreads();
#pragma unroll
    for (int i = 0; i < 4; i++) {
        int j = bx * 32 + ty + i * 8;
        int k = by * 32 + tx;
        g_W2t[j * 512 + k] = tile[tx][ty + i * 8];
    }
}

// ====================================================================
// 128x128-tile FFMA2 SGEMM (featW + gxx) — unchanged
// ====================================================================
__global__ void __launch_bounds__(256)
k_gemm128(int mode, const float* __restrict__ Aext,
          const float* __restrict__ Bmat, const float* __restrict__ bias,
          float* __restrict__ Cext,
          const float* __restrict__ embed, const int* __restrict__ captions,
          int M, int N, int K, int ldb, int ldc)
{
    const float* A; float* C;
    bool bnt = (mode == 2);
    if (mode == 0)      { A = Aext;   C = g_featW; }
    else if (mode == 1) { A = g_hist; C = Cext; }
    else                { A = nullptr; C = g_gxx; }

    __shared__ __align__(16) float2 As2[8][128];
    __shared__ __align__(16) float2 Bs2[8][128];

    int tid = threadIdx.x;
    int m0 = blockIdx.x * 128;
    int n0 = blockIdx.y * 128;
    int tx = tid & 15, ty = tid >> 4;

    int ia0 = tid, ia1 = tid + 256;
    int ar0 = ia0 >> 2, ar1 = ia1 >> 2;
    int ak0 = (ia0 & 3) * 4, ak1 = (ia1 & 3) * 4;
    const float *pArow0, *pArow1;
    if (mode == 2) {
        int m = m0 + ar0;
        pArow0 = embed + (long)captions[(m >> 5) * 33 + (m & 31)] * 512;
        m = m0 + ar1;
        pArow1 = embed + (long)captions[(m >> 5) * 33 + (m & 31)] * 512;
    } else {
        int m = min(m0 + ar0, M - 1); pArow0 = A + (long)m * 512;
        m = min(m0 + ar1, M - 1);     pArow1 = A + (long)m * 512;
    }

    int br0, bk0, br1, bk1;
    const float *pB0, *pB1;
    if (bnt) {
        br0 = ia0 >> 2; bk0 = (ia0 & 3) * 4;
        br1 = ia1 >> 2; bk1 = (ia1 & 3) * 4;
        pB0 = Bmat + (long)(n0 + br0) * ldb;
        pB1 = Bmat + (long)(n0 + br1) * ldb;
    } else {
        bk0 = ia0 >> 5; br0 = (ia0 & 31) * 4;
        bk1 = ia1 >> 5; br1 = (ia1 & 31) * 4;
        pB0 = Bmat + (long)bk0 * ldb + n0 + br0;
        pB1 = Bmat + (long)bk1 * ldb + n0 + br1;
    }
    bool nfull = (n0 + 128 <= N);

    ull acc[8][8];
#pragma unroll
    for (int i = 0; i < 8; i++)
#pragma unroll
        for (int j = 0; j < 8; j++) acc[i][j] = 0ull;

    float4 pa0 = *(const float4*)(pArow0 + ak0);
    float4 pa1 = *(const float4*)(pArow1 + ak1);
    float4 pb0, pb1;
    if (bnt) {
        pb0 = *(const float4*)(pB0 + bk0);
        pb1 = *(const float4*)(pB1 + bk1);
    } else if (nfull) {
        pb0 = *(const float4*)pB0;
        pb1 = *(const float4*)pB1;
    } else {
        int c0 = n0 + br0, c1 = n0 + br1;
        pb0.x = (c0+0<N)?pB0[0]:0.f; pb0.y = (c0+1<N)?pB0[1]:0.f;
        pb0.z = (c0+2<N)?pB0[2]:0.f; pb0.w = (c0+3<N)?pB0[3]:0.f;
        pb1.x = (c1+0<N)?pB1[0]:0.f; pb1.y = (c1+1<N)?pB1[1]:0.f;
        pb1.z = (c1+2<N)?pB1[2]:0.f; pb1.w = (c1+3<N)?pB1[3]:0.f;
    }

    for (int k0 = 0; k0 < K; k0 += 16) {
        As2[(ak0 >> 1)    ][ar0] = make_float2(pa0.x, pa0.y);
        As2[(ak0 >> 1) + 1][ar0] = make_float2(pa0.z, pa0.w);
        As2[(ak1 >> 1)    ][ar1] = make_float2(pa1.x, pa1.y);
        As2[(ak1 >> 1) + 1][ar1] = make_float2(pa1.z, pa1.w);
        if (bnt) {
            Bs2[(bk0 >> 1)    ][br0] = make_float2(pb0.x, pb0.y);
            Bs2[(bk0 >> 1) + 1][br0] = make_float2(pb0.z, pb0.w);
            Bs2[(bk1 >> 1)    ][br1] = make_float2(pb1.x, pb1.y);
            Bs2[(bk1 >> 1) + 1][br1] = make_float2(pb1.z, pb1.w);
        } else {
            float* q0 = (float*)&Bs2[bk0 >> 1][br0] + (bk0 & 1);
            q0[0] = pb0.x; q0[2] = pb0.y; q0[4] = pb0.z; q0[6] = pb0.w;
            float* q1 = (float*)&Bs2[bk1 >> 1][br1] + (bk1 & 1);
            q1[0] = pb1.x; q1[2] = pb1.y; q1[4] = pb1.z; q1[6] = pb1.w;
        }
        __syncthreads();

        if (k0 + 16 < K) {
            int kn = k0 + 16;
            pa0 = *(const float4*)(pArow0 + kn + ak0);
            pa1 = *(const float4*)(pArow1 + kn + ak1);
            if (bnt) {
                pb0 = *(const float4*)(pB0 + kn + bk0);
                pb1 = *(const float4*)(pB1 + kn + bk1);
            } else if (nfull) {
                pb0 = *(const float4*)(pB0 + (long)kn * ldb);
                pb1 = *(const float4*)(pB1 + (long)kn * ldb);
            } else {
                const float* r0 = pB0 + (long)kn * ldb;
                const float* r1 = pB1 + (long)kn * ldb;
                int c0 = n0 + br0, c1 = n0 + br1;
                pb0.x = (c0+0<N)?r0[0]:0.f; pb0.y = (c0+1<N)?r0[1]:0.f;
                pb0.z = (c0+2<N)?r0[2]:0.f; pb0.w = (c0+3<N)?r0[3]:0.f;
                pb1.x = (c1+0<N)?r1[0]:0.f; pb1.y = (c1+1<N)?r1[1]:0.f;
                pb1.z = (c1+2<N)?r1[2]:0.f; pb1.w = (c1+3<N)?r1[3]:0.f;
            }
        }

#pragma unroll
        for (int kp = 0; kp < 8; kp++) {
            ull a[8], b[8];
#pragma unroll
            for (int g = 0; g < 4; g++) {
                ulonglong2 av = *(const ulonglong2*)&As2[kp][g * 32 + ty * 2];
                a[g * 2] = av.x; a[g * 2 + 1] = av.y;
                ulonglong2 bv = *(const ulonglong2*)&Bs2[kp][g * 32 + tx * 2];
                b[g * 2] = bv.x; b[g * 2 + 1] = bv.y;
            }
#pragma unroll
            for (int i = 0; i < 8; i++)
#pragma unroll
                for (int j = 0; j < 8; j++)
                    FFMA2(acc[i][j], a[i], b[j], acc[i][j]);
        }
        __syncthreads();
    }

#pragma unroll
    for (int i = 0; i < 8; i++) {
        int mi = m0 + (i >> 1) * 32 + ty * 2 + (i & 1);
        if (mi >= M) continue;
#pragma unroll
        for (int j = 0; j < 8; j += 2) {
            int nj = n0 + (j >> 1) * 32 + tx * 2;
            if (nj + 1 < N) {
                float2 v;
                v.x = plo(acc[i][j])     + phi(acc[i][j])     + bias[nj];
                v.y = plo(acc[i][j + 1]) + phi(acc[i][j + 1]) + bias[nj + 1];
                *(float2*)&C[(long)mi * ldc + nj] = v;
            } else if (nj < N) {
                C[(long)mi * ldc + nj] = plo(acc[i][j]) + phi(acc[i][j]) + bias[nj];
            }
        }
    }
}

// ====================================================================
// Grid barrier: atomic arrive counter + separate release flag (R9)
// ====================================================================
__device__ __forceinline__ void gbar2(int idx, unsigned target)
{
    __syncthreads();
    if (threadIdx.x == 0) {
        unsigned old;
        asm volatile("atom.acq_rel.gpu.global.add.u32 %0, [%1], 1;"
                     : "=r"(old) : "l"(&g_arr[idx * 32]) : "memory");
        if (old == target - 1) {
            asm volatile("st.release.gpu.global.u32 [%0], %1;"
                         :: "l"(&g_rel[idx * 32]), "r"(target) : "memory");
        } else {
            unsigned v;
            do {
                asm volatile("ld.acquire.gpu.global.u32 %0, [%1];"
                             : "=r"(v) : "l"(&g_rel[idx * 32]));
            } while ((int)(v - target) < 0);
        }
    }
    __syncthreads();
}

// ====================================================================
// Persistent fused loop — exact R9 structure.
// ====================================================================
#define WST 520
#define HSS 136

__global__ void __launch_bounds__(NT)
k_loop(const float* __restrict__ features, const float* __restrict__ v_w,
       const float* __restrict__ W_hh, const float* __restrict__ W_ih,
       const float* __restrict__ b_hh)
{
    extern __shared__ float sm[];
    float* sW1 = sm;
    float* sW3 = sm + 24 * WST;
    float* hs  = sm + 36 * WST;

    int tid = threadIdx.x;
    int bid = blockIdx.x;
    bool light = (bid < 64);
    int j0 = bid * 4;

    if (light) {
        int cb = bid * 8;
        for (int i = tid; i < 8 * 512; i += NT) {
            int nl = i >> 9, k = i & 511;
            sW1[nl * WST + k] = g_W2t[(cb + nl) * 512 + k];
        }
    } else {
        int cb = (bid - 64) * 24;
        for (int i = tid; i < 24 * 512; i += NT) {
            int nl = i >> 9, k = i & 511;
            sW1[nl * WST + k] = W_hh[(long)(cb + nl) * 512 + k];
        }
    }
    for (int i = tid; i < 12 * 512; i += NT) {
        int rl = i >> 9, k = i & 511;
        int gate = rl >> 2, jl = rl & 3;
        sW3[rl * WST + k] = W_ih[(long)(gate * 512 + j0 + jl) * 1024 + 512 + k];
    }
    __syncthreads();

    int bq = tid >> 3;
    int nq = tid & 7;
    int b3 = tid >> 2;
    int jl3 = tid & 3;

    for (int t = 0; t < 32; t++) {
        if (light) {
            ull a0 = 0, a1 = 0;
            for (int c = 0; c < 4; c++) {
                for (int i = tid; i < 2048; i += NT) {
                    int b = i >> 5;
                    int kq4 = (i & 31) << 2;
                    float4 v;
                    if (t == 0) v = make_float4(0.f, 0.f, 0.f, 0.f);
                    else v = *(const float4*)&g_hist[(long)(b * 32 + t - 1) * 512 + c * 128 + kq4];
                    *(float4*)&hs[b * HSS + kq4] = v;
                }
                __syncthreads();
                const float* ap0 = &hs[(bq * 2) * HSS];
                const float* ap1 = ap0 + HSS;
                const float* wp  = &sW1[nq * WST + c * 128];
#pragma unroll 8
                for (int j = 0; j < 32; j++) {
                    ulonglong2 av0 = *(const ulonglong2*)(ap0 + 4 * j);
                    ulonglong2 av1 = *(const ulonglong2*)(ap1 + 4 * j);
                    ulonglong2 wv  = *(const ulonglong2*)(wp  + 4 * j);
                    FFMA2(a0, av0.x, wv.x, a0); FFMA2(a0, av0.y, wv.y, a0);
                    FFMA2(a1, av1.x, wv.x, a1); FFMA2(a1, av1.y, wv.y, a1);
                }
                __syncthreads();
            }
            int n = bid * 8 + nq;
            g_HAT[(bq * 2) * 512 + n]     = plo(a0) + phi(a0);
            g_HAT[(bq * 2 + 1) * 512 + n] = plo(a1) + phi(a1);

            gbar2(0, 64u * (t + 1));

            {
                int b = bid;
                float* hat = hs;
                float* vw  = hs + 512;
                float* sc  = hs + 1024;
                for (int j = tid; j < 512; j += NT) {
                    hat[j] = g_HAT[b * 512 + j];
                    vw[j]  = v_w[j];
                }
                __syncthreads();
                int warp = tid >> 5, lane = tid & 31;
                for (int r = warp; r < 49; r += 8) {
                    const float* fw = g_featW + (long)(b * 49 + r) * 512;
                    float p = 0.f;
                    for (int j = lane; j < 512; j += 32)
                        p += ftanh(fw[j] + hat[j]) * vw[j];
#pragma unroll
                    for (int o = 16; o; o >>= 1) p += __shfl_xor_sync(0xffffffffu, p, o);
                    if (lane == 0) sc[r] = p;
                }
                __syncthreads();
                if (tid < 32) {
                    float s0 = (tid < 49) ? sc[tid] : -1e30f;
                    float s1 = (tid + 32 < 49) ? sc[tid + 32] : -1e30f;
                    float mx = fmaxf(s0, s1);
#pragma unroll
                    for (int o = 16; o; o >>= 1) mx = fmaxf(mx, __shfl_xor_sync(0xffffffffu, mx, o));
                    float e0 = (tid < 49) ? fexpa(s0 - mx) : 0.f;
                    float e1 = (tid + 32 < 49) ? fexpa(s1 - mx) : 0.f;
                    float s = e0 + e1;
#pragma unroll
                    for (int o = 16; o; o >>= 1) s += __shfl_xor_sync(0xffffffffu, s, o);
                    float inv = 1.f / s;
                    if (tid < 49) sc[tid] = e0 * inv;
                    if (tid + 32 < 49) sc[tid + 32] = e1 * inv;
                }
                __syncthreads();
                for (int j = tid; j < 512; j += NT) {
                    const float* fb = features + (long)b * 49 * 512 + j;
                    float acc = 0.f;
#pragma unroll 7
                    for (int r = 0; r < 49; r++) acc = fmaf(sc[r], fb[r * 512], acc);
                    g_ctx[b * 512 + j] = acc;
                }
            }
        } else {
            ull a00 = 0, a01 = 0, a02 = 0, a10 = 0, a11 = 0, a12 = 0;
            for (int c = 0; c < 4; c++) {
                for (int i = tid; i < 2048; i += NT) {
                    int b = i >> 5;
                    int kq4 = (i & 31) << 2;
                    float4 v;
                    if (t == 0) v = make_float4(0.f, 0.f, 0.f, 0.f);
                    else v = *(const float4*)&g_hist[(long)(b * 32 + t - 1) * 512 + c * 128 + kq4];
                    *(float4*)&hs[b * HSS + kq4] = v;
                }
                __syncthreads();
                const float* ap0 = &hs[(bq * 2) * HSS];
                const float* ap1 = ap0 + HSS;
                const float* wp0 = &sW1[(nq * 3 + 0) * WST + c * 128];
                const float* wp1 = wp0 + WST;
                const float* wp2 = wp1 + WST;
#pragma unroll 4
                for (int j = 0; j < 32; j++) {
                    ulonglong2 av0 = *(const ulonglong2*)(ap0 + 4 * j);
                    ulonglong2 av1 = *(const ulonglong2*)(ap1 + 4 * j);
                    ulonglong2 w0 = *(const ulonglong2*)(wp0 + 4 * j);
                    ulonglong2 w1 = *(const ulonglong2*)(wp1 + 4 * j);
                    ulonglong2 w2 = *(const ulonglong2*)(wp2 + 4 * j);
                    FFMA2(a00, av0.x, w0.x, a00); FFMA2(a00, av0.y, w0.y, a00);
                    FFMA2(a01, av0.x, w1.x, a01); FFMA2(a01, av0.y, w1.y, a01);
                    FFMA2(a02, av0.x, w2.x, a02); FFMA2(a02, av0.y, w2.y, a02);
                    FFMA2(a10, av1.x, w0.x, a10); FFMA2(a10, av1.y, w0.y, a10);
                    FFMA2(a11, av1.x, w1.x, a11); FFMA2(a11, av1.y, w1.y, a11);
                    FFMA2(a12, av1.x, w2.x, a12); FFMA2(a12, av1.y, w2.y, a12);
                }
                __syncthreads();
            }
            int col = (bid - 64) * 24 + nq * 3;
            int b0 = bq * 2, b1r = bq * 2 + 1;
            g_GH[b0 * 1536 + col]     = plo(a00) + phi(a00);
            g_GH[b0 * 1536 + col + 1] = plo(a01) + phi(a01);
            g_GH[b0 * 1536 + col + 2] = plo(a02) + phi(a02);
            g_GH[b1r * 1536 + col]     = plo(a10) + phi(a10);
            g_GH[b1r * 1536 + col + 1] = plo(a11) + phi(a11);
            g_GH[b1r * 1536 + col + 2] = plo(a12) + phi(a12);
        }

        gbar2(1, 128u * (t + 1));

        ull cr = 0, cz = 0, cn = 0;
        for (int c = 0; c < 4; c++) {
            for (int i = tid; i < 2048; i += NT) {
                int b = i >> 5;
                int kq4 = (i & 31) << 2;
                *(float4*)&hs[b * HSS + kq4] =
                    *(const float4*)&g_ctx[b * 512 + c * 128 + kq4];
            }
            __syncthreads();
            const float* ap = &hs[b3 * HSS];
            const float* wr = &sW3[(0 + jl3) * WST + c * 128];
            const float* wz = &sW3[(4 + jl3) * WST + c * 128];
            const float* wn = &sW3[(8 + jl3) * WST + c * 128];
#pragma unroll 8
            for (int j = 0; j < 32; j++) {
                ulonglong2 av = *(const ulonglong2*)(ap + 4 * j);
                ulonglong2 w0 = *(const ulonglong2*)(wr + 4 * j);
                ulonglong2 w1 = *(const ulonglong2*)(wz + 4 * j);
                ulonglong2 w2 = *(const ulonglong2*)(wn + 4 * j);
                FFMA2(cr, av.x, w0.x, cr); FFMA2(cr, av.y, w0.y, cr);
                FFMA2(cz, av.x, w1.x, cz); FFMA2(cz, av.y, w1.y, cz);
                FFMA2(cn, av.x, w2.x, cn); FFMA2(cn, av.y, w2.y, cn);
            }
            __syncthreads();
        }
        {
            int j = j0 + jl3;
            int b = b3;
            int m = b * 32 + t;
            float xr = plo(cr) + phi(cr);
            float xz = plo(cz) + phi(cz);
            float xn = plo(cn) + phi(cn);
            float gxr = g_gxx[(long)m * 1536 + j]        + xr;
            float gxz = g_gxx[(long)m * 1536 + 512 + j]  + xz;
            float gxn = g_gxx[(long)m * 1536 + 1024 + j] + xn;
            float ghr = g_GH[b * 1536 + j]        + b_hh[j];
            float ghz = g_GH[b * 1536 + 512 + j]  + b_hh[512 + j];
            float ghn = g_GH[b * 1536 + 1024 + j] + b_hh[1024 + j];
            float rg = fsigmoid(gxr + ghr);
            float zg = fsigmoid(gxz + ghz);
            float ng = ftanh(gxn + rg * ghn);
            float hp = (t == 0) ? 0.f : g_hist[(long)(m - 1) * 512 + j];
            g_hist[(long)m * 512 + j] = (1.f - zg) * ng + zg * hp;
        }

        gbar2(2, 128u * (t + 1));
    }
}

// ====================================================================
// bf16 split conversions (separate, as in R9)
// ====================================================================
__global__ void k_convA()
{
    int idx = blockIdx.x * 256 + threadIdx.x;
    int m = idx >> 9, k = idx & 511;
    float a = g_hist[(long)m * 512 + k];
    __nv_bfloat16 hi = __float2bfloat16_rn(a);
    __nv_bfloat16 lo = __float2bfloat16_rn(a - __bfloat162float(hi));
    g_Abig[(long)m * 1536 + k]        = hi;
    g_Abig[(long)m * 1536 + 512 + k]  = lo;
    g_Abig[(long)m * 1536 + 1024 + k] = hi;
}

__global__ void k_convB(const float* __restrict__ fc_W)
{
    __shared__ float tile[32][33];
    int n0 = blockIdx.x * 32, k0 = blockIdx.y * 32;
    int tx = threadIdx.x, ty = threadIdx.y;
#pragma unroll
    for (int i = 0; i < 4; i++) {
        int k = k0 + ty + i * 8;
        int n = n0 + tx;
        tile[ty + i * 8][tx] = (n < 10000) ? fc_W[(long)k * 10000 + n] : 0.f;
    }
    __syncthreads();
#pragma unroll
    for (int i = 0; i < 4; i++) {
        int n = n0 + ty + i * 8;
        int k = k0 + tx;
        float v = tile[tx][ty + i * 8];
        __nv_bfloat16 hi = __float2bfloat16_rn(v);
        __nv_bfloat16 lo = __float2bfloat16_rn(v - __bfloat162float(hi));
        g_Bbig[(long)n * 1536 + k]        = hi;
        g_Bbig[(long)n * 1536 + 512 + k]  = hi;
        g_Bbig[(long)n * 1536 + 1024 + k] = lo;
    }
}

// ====================================================================
// fc GEMM via mma.sync bf16 + cp.async — unchanged (R9)
// ====================================================================
#define LDSM4(r0,r1,r2,r3,addr) \
    asm volatile("ldmatrix.sync.aligned.m8n8.x4.shared.b16 {%0,%1,%2,%3}, [%4];" \
        : "=r"(r0), "=r"(r1), "=r"(r2), "=r"(r3) : "r"(addr))

#define MMA16816(d,a0,a1,a2,a3,b0,b1) \
    asm volatile("mma.sync.aligned.m16n8k16.row.col.f32.bf16.bf16.f32 " \
        "{%0,%1,%2,%3}, {%4,%5,%6,%7}, {%8,%9}, {%0,%1,%2,%3};" \
        : "+f"((d)[0]), "+f"((d)[1]), "+f"((d)[2]), "+f"((d)[3]) \
        : "r"(a0), "r"(a1), "r"(a2), "r"(a3), "r"(b0), "r"(b1))

#define CPA16(saddr, gptr) \
    asm volatile("cp.async.cg.shared.global [%0], [%1], 16;" :: "r"(saddr), "l"(gptr))

#define FC_ABUF 18432u
#define FC_BBASE (2u * FC_ABUF)
#define FC_SMEM (4u * FC_ABUF)

#define FC_ISSUE(chv, bufv)                                                     \
    do {                                                                         \
        int _cb = (chv) * 64;                                                    \
        _Pragma("unroll")                                                        \
        for (int _p = 0; _p < 4; _p++) {                                         \
            int _i = tid + _p * 256;                                             \
            int _row = _i >> 3, _c = _i & 7;                                     \
            CPA16(sb + (bufv) * FC_ABUF + _row * 144 + _c * 16,                  \
                  gA + (long)_row * 1536 + _cb + _c * 8);                        \
            CPA16(sb + FC_BBASE + (bufv) * FC_ABUF + _row * 144 + _c * 16,       \
                  gB + (long)_row * 1536 + _cb + _c * 8);                        \
        }                                                                        \
    } while (0)

__global__ void __launch_bounds__(256)
k_fc_mma(const float* __restrict__ fc_b, float* __restrict__ out)
{
    extern __shared__ __align__(16) char smc[];
    u32 sb;
    asm("{ .reg .u64 t; cvta.to.shared.u64 t, %1; cvt.u32.u64 %0, t; }" : "=r"(sb) : "l"(smc));

    int tid = threadIdx.x;
    int wid = tid >> 5, lane = tid & 31;
    int m0 = blockIdx.x * 128;
    int n0 = blockIdx.y * 128;
    int wm = (wid >> 2) * 64;
    int wn = (wid & 3) * 32;

    const __nv_bfloat16* gA = g_Abig + (long)m0 * 1536;
    const __nv_bfloat16* gB = g_Bbig + (long)n0 * 1536;

    u32 lmoff = (lane & 15) * 144 + (lane >> 4) * 16;

    float acc[4][4][4];
#pragma unroll
    for (int i = 0; i < 4; i++)
#pragma unroll
        for (int j = 0; j < 4; j++)
#pragma unroll
            for (int c = 0; c < 4; c++) acc[i][j][c] = 0.f;

    FC_ISSUE(0, 0);
    asm volatile("cp.async.commit_group;" ::: "memory");
    FC_ISSUE(1, 1);
    asm volatile("cp.async.commit_group;" ::: "memory");

    for (int ch = 0; ch < 24; ch++) {
        u32 buf = ch & 1;
        asm volatile("cp.async.wait_group 1;" ::: "memory");
        __syncthreads();

        u32 abase = sb + buf * FC_ABUF + wm * 144 + lmoff;
        u32 bbase = sb + FC_BBASE + buf * FC_ABUF + wn * 144 + lmoff;
#pragma unroll
        for (int ks = 0; ks < 4; ks++) {
            u32 a[4][4], b[2][4];
#pragma unroll
            for (int mt = 0; mt < 4; mt++)
                LDSM4(a[mt][0], a[mt][1], a[mt][2], a[mt][3],
                      abase + mt * (16 * 144) + ks * 32);
#pragma unroll
            for (int nt2 = 0; nt2 < 2; nt2++)
                LDSM4(b[nt2][0], b[nt2][1], b[nt2][2], b[nt2][3],
                      bbase + nt2 * (16 * 144) + ks * 32);
#pragma unroll
            for (int mt = 0; mt < 4; mt++)
#pragma unroll
                for (int nt = 0; nt < 4; nt++) {
                    int n2 = nt >> 1, ns = nt & 1;
                    MMA16816(acc[mt][nt], a[mt][0], a[mt][1], a[mt][2], a[mt][3],
                             b[n2][ns], b[n2][ns + 2]);
                }
        }
        __syncthreads();

        if (ch + 2 < 24) FC_ISSUE(ch + 2, buf);
        asm volatile("cp.async.commit_group;" ::: "memory");
    }

#pragma unroll
    for (int mt = 0; mt < 4; mt++) {
        int rm = m0 + wm + mt * 16 + (lane >> 2);
#pragma unroll
        for (int nt = 0; nt < 4; nt++) {
            int cn = n0 + wn + nt * 8 + (lane & 3) * 2;
            if (cn < 10000) {
                float2 v0, v1;
                float bb0 = fc_b[cn], bb1 = fc_b[cn + 1];
                v0.x = acc[mt][nt][0] + bb0; v0.y = acc[mt][nt][1] + bb1;
                v1.x = acc[mt][nt][2] + bb0; v1.y = acc[mt][nt][3] + bb1;
                *(float2*)&out[(long)rm * 10000 + cn] = v0;
                *(float2*)&out[(long)(rm + 8) * 10000 + cn] = v1;
            }
        }
    }
}

// ====================================================================
extern "C" void kernel_launch(void* const* d_in, const int* in_sizes, int n_in,
                              void* d_out, int out_size)
{
    const float* features = (const float*)d_in[0];
    const int*   captions = (const int*)d_in[1];
    const float* embed    = (const float*)d_in[2];
    const float* attn_W   = (const float*)d_in[3];
    const float* attn_b   = (const float*)d_in[4];
    const float* v_w      = (const float*)d_in[5];
    const float* W_ih     = (const float*)d_in[6];
    const float* W_hh     = (const float*)d_in[7];
    const float* b_ih     = (const float*)d_in[8];
    const float* b_hh     = (const float*)d_in[9];
    const float* fc_W     = (const float*)d_in[10];
    const float* fc_b     = (const float*)d_in[11];
    float* out = (float*)d_out;

    const int LOOP_SMEM = (36 * WST + 64 * HSS) * 4;   // 109,696 B
    cudaFuncSetAttribute(k_loop, cudaFuncAttributeMaxDynamicSharedMemorySize, LOOP_SMEM);
    cudaFuncSetAttribute(k_fc_mma, cudaFuncAttributeMaxDynamicSharedMemorySize, FC_SMEM);

    // launch 1: transpose (+ barrier reset)
    k_transpose_w2<<<dim3(16, 16), dim3(32, 8)>>>(attn_W);

    // launch 2: featW = features @ attn_W[:512] + attn_b
    k_gemm128<<<dim3(25, 4), 256>>>(0, features, attn_W, attn_b, nullptr,
                                    nullptr, nullptr, 3136, 512, 512, 512, 512);

    // launch 3: gx_x = gather(embed, captions) @ W_ih[:, :512]^T + b_ih
    k_gemm128<<<dim3(16, 12), 256>>>(2, nullptr, W_ih, b_ih, nullptr,
                                     embed, captions, 2048, 1536, 512, 1024, 1536);

    // launch 4: persistent fused 32-step scan  <-- ncu capture slot
    k_loop<<<NB, NT, LOOP_SMEM>>>(features, v_w, W_hh, W_ih, b_hh);

    // launch 5: B' split
    k_convB<<<dim3(320, 16), dim3(32, 8)>>>(fc_W);

    // launch 6: A' split from hist
    k_convA<<<4096, 256>>>();

    // launch 7: out = Abig @ Bbig^T + fc_b
    k_fc_mma<<<dim3(16, 80), 256, FC_SMEM>>>(fc_b, out);
}